// round 7
// baseline (speedup 1.0000x reference)
#include <cuda_runtime.h>
#include <cuda_bf16.h>
#include <cstdint>

// Problem shape (fixed by the dataset)
#define BB 64
#define CC 256
#define HH 80
#define WW 80
#define NN 100
#define IMG 640.0f

#define NPLANES (BB * CC)          // 16384 planes
#define PLANE_ELEMS (HH * WW)      // 6400 floats
#define PSTRIDE 84                 // padded smem row stride (floats)
#define PBUF (HH * PSTRIDE)        // 6720 floats per buffer (26.88 KB)
#define NG 4                       // groups per CTA
#define GW 6                       // warps per group: 3 loader + 3 compute
#define GRID 152                   // persistent, one CTA per SM
#define TPB (NG * GW * 32)         // 768 threads
#define STRIDEP (GRID * NG)        // 608 groups chip-wide
#define PF 20                      // loader rotating-prefetch depth (regs)

__device__ __forceinline__ void named_bar(int id, int count) {
    asm volatile("bar.sync %0, %1;" :: "r"(id), "r"(count) : "memory");
}

// Loader side: column cumsum (axis y) fused with GMEM load, into padded buf.
// Lane lt<80 owns column lt; at fixed y lanes hit consecutive banks.
// PF-deep rotating prefetch keeps ~PF loads in flight per lane, FADD chain only.
__device__ __forceinline__ void pass1_load_colscan(const float* __restrict__ plane,
                                                   float* __restrict__ S, int lt) {
    if (lt < WW) {
        float buf[PF];
        #pragma unroll
        for (int d = 0; d < PF; ++d)
            buf[d] = __ldg(plane + d * WW + lt);

        float acc = 0.0f;
        #pragma unroll
        for (int y = 0; y < HH; ++y) {
            float v = buf[y % PF];
            const int yn = y + PF;
            if (yn < HH)
                buf[y % PF] = __ldg(plane + yn * WW + lt);
            acc += v;
            S[y * PSTRIDE + lt] = acc;
        }
    }
}

__global__ __launch_bounds__(TPB, 1)
void roi_pool_kernel(const float* __restrict__ fmap,
                     const float* __restrict__ boxes,
                     float* __restrict__ out)
{
    extern __shared__ __align__(16) float P[];   // [NG][2][PBUF] = 215 KB

    const int tid  = threadIdx.x;
    const int wid  = tid >> 5;
    const int lane = tid & 31;
    const int bid  = blockIdx.x;

    const int g  = wid / GW;                 // group 0..3
    const int wg = wid % GW;                 // warp in group 0..5
    const bool loader = (wg < 3);
    const int lt = wg * 32 + lane;           // loader lane id 0..95
    const int ct = (wg - 3) * 32 + lane;     // compute lane id 0..95

    float* const B0 = P + (size_t)(g * 2) * PBUF;
    float* const B1 = B0 + PBUF;
    const int G = bid * NG + g;              // global group id 0..607

    // Prologue: loaders fill buffer 0 with plane 0's column-scan.
    if (loader && G < NPLANES)
        pass1_load_colscan(fmap + (size_t)G * PLANE_ELEMS, B0, lt);

    for (int it = 0; ; ++it) {
        const int p = G + it * STRIDEP;
        if (p >= NPLANES) break;

        // buf(it&1) ready (loaders wrote it last iteration / prologue);
        // buf((it+1)&1) free (compute finished it at iteration it-1).
        // bar.sync also drains the loaders' pending STS.
        named_bar(1 + g, GW * 32);

        if (loader) {
            const int pn = p + STRIDEP;
            if (pn < NPLANES)
                pass1_load_colscan(fmap + (size_t)pn * PLANE_ELEMS,
                                   ((it + 1) & 1) ? B1 : B0, lt);
        } else {
            float* S = (it & 1) ? B1 : B0;

            // ===== Pass 2: row cumsum (axis x), float4, in place. =====
            // Row stride 21 float4 -> conflict-free phasing (proven R1/R4).
            if (ct < HH) {
                float4* row = reinterpret_cast<float4*>(S + ct * PSTRIDE);
                float acc = 0.0f;
                #pragma unroll
                for (int q = 0; q < WW / 4; ++q) {
                    float4 v4 = row[q];
                    v4.x += acc;
                    v4.y += v4.x;
                    v4.z += v4.y;
                    v4.w += v4.z;
                    acc = v4.w;
                    row[q] = v4;
                }
            }
            named_bar(1 + NG + g, 96);   // compute-warps-only barrier

            // ===== Pass 3: evaluate 100 boxes (2 rounds over 96 lanes). =====
            const int b = p / CC;
            const int c = p % CC;
            #pragma unroll
            for (int r0 = 0; r0 < 2; ++r0) {
                const int n = ct + r0 * 96;
                if (n < NN) {
                    float4 bx = reinterpret_cast<const float4*>(boxes)[b * NN + n];
                    // Reference math exactly: (coord/640)*80 fp32 RN, int
                    // truncation (non-negative => floor), clip to [0, dim].
                    int x1 = (int)__fmul_rn(__fdiv_rn(bx.x, IMG), (float)WW);
                    int y1 = (int)__fmul_rn(__fdiv_rn(bx.y, IMG), (float)HH);
                    int x2 = (int)__fmul_rn(__fdiv_rn(bx.z, IMG), (float)WW);
                    int y2 = (int)__fmul_rn(__fdiv_rn(bx.w, IMG), (float)HH);
                    x1 = min(max(x1, 0), WW);
                    y1 = min(max(y1, 0), HH);
                    x2 = min(max(x2, 0), WW);
                    y2 = min(max(y2, 0), HH);

                    const int dy = y2 - y1;
                    const int dx = x2 - x1;
                    float r = 0.0f;
                    if (dy > 0 && dx > 0) {
                        // Inclusive integral -> exclusive corners; border 0.
                        float s22 = S[(y2 - 1) * PSTRIDE + (x2 - 1)];
                        float s12 = (y1 > 0) ? S[(y1 - 1) * PSTRIDE + (x2 - 1)] : 0.0f;
                        float s21 = (x1 > 0) ? S[(y2 - 1) * PSTRIDE + (x1 - 1)] : 0.0f;
                        float s11 = (y1 > 0 && x1 > 0) ? S[(y1 - 1) * PSTRIDE + (x1 - 1)] : 0.0f;
                        r = __fdiv_rn(s22 - s12 - s21 + s11, (float)(dy * dx));
                    }
                    out[((size_t)b * NN + n) * CC + c] = r;
                }
            }
        }
        // Loop back: group barrier at top orders compute's reads of buf(it&1)
        // before loaders overwrite it at iteration it+2, and loaders' writes
        // of buf((it+1)&1) before compute reads them at it+1.
    }
}

extern "C" void kernel_launch(void* const* d_in, const int* in_sizes, int n_in,
                              void* d_out, int out_size)
{
    const float* fmap  = (const float*)d_in[0];   // [64,256,80,80]
    const float* boxes = (const float*)d_in[1];   // [64,100,4]
    float* out = (float*)d_out;                   // [64,100,256]

    const int smem_bytes = NG * 2 * PBUF * sizeof(float);   // 215040
    cudaFuncSetAttribute(roi_pool_kernel,
                         cudaFuncAttributeMaxDynamicSharedMemorySize,
                         smem_bytes);

    roi_pool_kernel<<<GRID, TPB, smem_bytes>>>(fmap, boxes, out);
}